// round 12
// baseline (speedup 1.0000x reference)
#include <cuda_runtime.h>
#include <math.h>

// Fixed shapes: x (4, 32, 8192, 64) fp32, token_positions = arange(8192)
#define SEQ        8192
#define NF4_ROW    16                    // 64 floats / 4 per row
#define SLICE_F4   (SEQ * NF4_ROW)       // 131072 float4 per (b,h) slice
#define N4_TOTAL   (128 * SLICE_F4)      // 16,777,216 float4 total
#define QUARTER_F4 (N4_TOTAL / 4)        // = 32 * SLICE_F4 -> same (p,j)
#define LOG2_THETA 13.2877123795494489f  // log2(10000), fp32

// Staggered 4-stream pipeline. vs R9 (2 streams, 82.6% DRAM): halves trig/byte
// and keeps loads in flight DURING the store phase. vs R10 (4 front-batched,
// 80.8%): never queues more than 2 LDG.128 per burst, avoiding the L1tex
// queue-depth penalty. Plain loads/stores (R8/R11: every cache hint lost).
__global__ void __launch_bounds__(256, 6)
rope_pipe4(const float4* __restrict__ x, float4* __restrict__ out,
           const int* __restrict__ pos) {
    int i = blockIdx.x * 256 + threadIdx.x;      // 0 .. QUARTER_F4-1
    int j = i & (NF4_ROW - 1);                   // float4 within row
    int p = (i >> 4) & (SEQ - 1);                // seq position

    // ---- Burst 1: first two streams ----
    float4 v0 = x[i];
    float4 v1 = x[i + 1 * QUARTER_F4];

    // ---- Trig (covered by v0/v1 DRAM latency); shared by all 4 streams ----
    float posf = (float)__ldg(&pos[p]);
    float invf0 = exp2f(-(float)(2 * j)     * (LOG2_THETA / 32.0f));
    float invf1 = exp2f(-(float)(2 * j + 1) * (LOG2_THETA / 32.0f));
    float c0, s0, c1, s1;
    sincosf(posf * invf0, &s0, &c0);
    sincosf(posf * invf1, &s1, &c1);

    // ---- Burst 2: next two streams (in flight behind the stores below) ----
    float4 v2 = x[i + 2 * QUARTER_F4];
    float4 v3 = x[i + 3 * QUARTER_F4];

    // ---- Rotate + store streams 0,1 while v2/v3 loads are outstanding ----
    float4 o;
    o.x = c0 * v0.x - s0 * v0.y;  o.y = s0 * v0.x + c0 * v0.y;
    o.z = c1 * v0.z - s1 * v0.w;  o.w = s1 * v0.z + c1 * v0.w;
    out[i] = o;
    o.x = c0 * v1.x - s0 * v1.y;  o.y = s0 * v1.x + c0 * v1.y;
    o.z = c1 * v1.z - s1 * v1.w;  o.w = s1 * v1.z + c1 * v1.w;
    out[i + 1 * QUARTER_F4] = o;

    // ---- Rotate + store streams 2,3 ----
    o.x = c0 * v2.x - s0 * v2.y;  o.y = s0 * v2.x + c0 * v2.y;
    o.z = c1 * v2.z - s1 * v2.w;  o.w = s1 * v2.z + c1 * v2.w;
    out[i + 2 * QUARTER_F4] = o;
    o.x = c0 * v3.x - s0 * v3.y;  o.y = s0 * v3.x + c0 * v3.y;
    o.z = c1 * v3.z - s1 * v3.w;  o.w = s1 * v3.z + c1 * v3.w;
    out[i + 3 * QUARTER_F4] = o;
}

extern "C" void kernel_launch(void* const* d_in, const int* in_sizes, int n_in,
                              void* d_out, int out_size) {
    const float4* x   = (const float4*)d_in[0];
    const int*    pos = (const int*)d_in[1];
    float4*       out = (float4*)d_out;

    // 4,194,304 threads = 16384 blocks of 256
    rope_pipe4<<<QUARTER_F4 / 256, 256>>>(x, out, pos);
}